// round 4
// baseline (speedup 1.0000x reference)
#include <cuda_runtime.h>
#include <cstddef>

#define THREADS   256
#define BM        32
#define SX_STRIDE 257   // 256 + 1 pad (odd -> conflict-free scalar LDS)
#define SW_STRIDE 65    // 64 + 1 pad

#define B_TARGETS 4096
#define L1_ROWS   (B_TARGETS * 11)   // 45056

// Layer-1 hidden representations scratch (23 MB). Device global per harness rules.
__device__ __align__(256) float g_h1[L1_ROWS * 128];

// Fused: build X tile [BM x 256] in shared (gather + mean), then
// Y = l2norm_rows(relu(X @ W^T + bias)), Y is [BM x 128].
// LAYER 0: X rows are level-1 nodes (self feat || mean of 25 nbr feats).
// LAYER 1: X rows are targets       (h1[b,0]   || mean of h1[b,1..10]).
template <int LAYER>
__global__ __launch_bounds__(THREADS, 2)
void sage_layer(const float* __restrict__ src,
                const int*   __restrict__ nodes,
                const int*   __restrict__ nbr1,
                const int*   __restrict__ nbr0,
                const float* __restrict__ W,      // [128][256] row-major
                const float* __restrict__ bias,   // [128]
                float*       __restrict__ out)    // [rows][128]
{
    extern __shared__ float smem[];
    float* sX    = smem;                           // BM * SX_STRIDE
    float* sW    = sX + BM * SX_STRIDE;            // 128 * SW_STRIDE
    float* sBias = sW + 128 * SW_STRIDE;           // 128
    float* sPart = sBias + 128;                    // 16 * 32
    float* sInv  = sPart + 16 * 32;                // 32

    const int tid  = threadIdx.x;
    const int warp = tid >> 5;
    const int lane = tid & 31;
    const int m0   = blockIdx.x * BM;

    if (tid < 128) sBias[tid] = bias[tid];

    // ---------------- gather phase: warp w builds local rows w*4 .. w*4+3 ----
    #pragma unroll
    for (int r = 0; r < 4; ++r) {
        const int mL = warp * 4 + r;
        float4 self;
        float4 acc = make_float4(0.f, 0.f, 0.f, 0.f);

        if (LAYER == 0) {
            const int j   = m0 + mL;        // level-1 node id in [0, 45056)
            const int b   = j / 11;
            const int col = j - b * 11;
            const int sidx = (col == 0) ? __ldg(&nodes[b])
                                        : __ldg(&nbr1[b * 10 + col - 1]);
            self = ((const float4*)(src + (size_t)sidx * 128))[lane];

            const int* nb = nbr0 + (size_t)j * 25;
            #pragma unroll
            for (int s = 0; s < 25; ++s) {
                const int ni = __ldg(&nb[s]);
                float4 v = ((const float4*)(src + (size_t)ni * 128))[lane];
                acc.x += v.x; acc.y += v.y; acc.z += v.z; acc.w += v.w;
            }
            const float sc = 1.0f / 25.0f;
            acc.x *= sc; acc.y *= sc; acc.z *= sc; acc.w *= sc;
        } else {
            const int b = m0 + mL;          // target index
            const float* base = src + (size_t)b * (11 * 128);
            self = ((const float4*)base)[lane];
            #pragma unroll
            for (int s = 1; s <= 10; ++s) {
                float4 v = ((const float4*)(base + s * 128))[lane];
                acc.x += v.x; acc.y += v.y; acc.z += v.z; acc.w += v.w;
            }
            const float sc = 0.1f;
            acc.x *= sc; acc.y *= sc; acc.z *= sc; acc.w *= sc;
        }

        float* dst = sX + mL * SX_STRIDE;
        dst[4 * lane + 0] = self.x;
        dst[4 * lane + 1] = self.y;
        dst[4 * lane + 2] = self.z;
        dst[4 * lane + 3] = self.w;
        dst[128 + 4 * lane + 0] = acc.x;
        dst[128 + 4 * lane + 1] = acc.y;
        dst[128 + 4 * lane + 2] = acc.z;
        dst[128 + 4 * lane + 3] = acc.w;
    }

    // ---------------- GEMM: accv[mi][j] = sum_k X[2*mt+mi][k] * W[nt*8+j][k]
    const int nt = tid >> 4;   // 0..15 (warp spans 2 nt values -> b-loads broadcast)
    const int mt = tid & 15;   // 0..15

    float accv[2][8];
    #pragma unroll
    for (int mi = 0; mi < 2; ++mi)
        #pragma unroll
        for (int j = 0; j < 8; ++j) accv[mi][j] = 0.f;

    #pragma unroll 1
    for (int kc = 0; kc < 4; ++kc) {
        __syncthreads();   // kc==0: gather done; kc>0: protect sW overwrite
        for (int i = tid; i < 128 * 64; i += THREADS) {
            const int h = i >> 6, kk = i & 63;
            sW[h * SW_STRIDE + kk] = __ldg(&W[h * 256 + kc * 64 + kk]);
        }
        __syncthreads();

        const float* a0p = sX + (mt * 2 + 0) * SX_STRIDE + kc * 64;
        const float* a1p = sX + (mt * 2 + 1) * SX_STRIDE + kc * 64;
        const float* bp  = sW + (nt * 8) * SW_STRIDE;

        #pragma unroll 4
        for (int kk = 0; kk < 64; ++kk) {
            const float a0 = a0p[kk];
            const float a1 = a1p[kk];
            #pragma unroll
            for (int j = 0; j < 8; ++j) {
                const float bv = bp[j * SW_STRIDE + kk];
                accv[0][j] += a0 * bv;
                accv[1][j] += a1 * bv;
            }
        }
    }

    // ---------------- epilogue: bias + relu + row L2 norm + store ----------
    float ss0 = 0.f, ss1 = 0.f;
    #pragma unroll
    for (int j = 0; j < 8; ++j) {
        const float bb = sBias[nt * 8 + j];
        float v0 = fmaxf(accv[0][j] + bb, 0.f);
        float v1 = fmaxf(accv[1][j] + bb, 0.f);
        accv[0][j] = v0;
        accv[1][j] = v1;
        ss0 += v0 * v0;
        ss1 += v1 * v1;
    }
    sPart[nt * 32 + mt * 2 + 0] = ss0;
    sPart[nt * 32 + mt * 2 + 1] = ss1;
    __syncthreads();

    if (tid < 32) {
        float t = 0.f;
        #pragma unroll
        for (int n = 0; n < 16; ++n) t += sPart[n * 32 + tid];
        sInv[tid] = 1.0f / fmaxf(sqrtf(t), 1e-12f);
    }
    __syncthreads();

    #pragma unroll
    for (int mi = 0; mi < 2; ++mi) {
        const int m = mt * 2 + mi;
        const float inv = sInv[m];
        float* op = out + (size_t)(m0 + m) * 128 + nt * 8;
        float4 o;
        o.x = accv[mi][0] * inv; o.y = accv[mi][1] * inv;
        o.z = accv[mi][2] * inv; o.w = accv[mi][3] * inv;
        ((float4*)op)[0] = o;
        o.x = accv[mi][4] * inv; o.y = accv[mi][5] * inv;
        o.z = accv[mi][6] * inv; o.w = accv[mi][7] * inv;
        ((float4*)op)[1] = o;
    }
}

extern "C" void kernel_launch(void* const* d_in, const int* in_sizes, int n_in,
                              void* d_out, int out_size)
{
    (void)in_sizes; (void)n_in; (void)out_size;

    const float* features = (const float*)d_in[0];
    const float* W0       = (const float*)d_in[1];
    const float* b0       = (const float*)d_in[2];
    const float* W1       = (const float*)d_in[3];
    const float* b1       = (const float*)d_in[4];
    const int*   nodes    = (const int*)d_in[5];
    const int*   nbr1     = (const int*)d_in[6];
    const int*   nbr0     = (const int*)d_in[7];
    float*       out      = (float*)d_out;

    const int SMEM = (BM * SX_STRIDE + 128 * SW_STRIDE + 128 + 16 * 32 + 32)
                     * (int)sizeof(float);   // 68864 B

    cudaFuncSetAttribute(sage_layer<0>,
                         cudaFuncAttributeMaxDynamicSharedMemorySize, SMEM);
    cudaFuncSetAttribute(sage_layer<1>,
                         cudaFuncAttributeMaxDynamicSharedMemorySize, SMEM);

    float* h1 = nullptr;
    cudaGetSymbolAddress((void**)&h1, g_h1);

    sage_layer<0><<<L1_ROWS / BM, THREADS, SMEM>>>(
        features, nodes, nbr1, nbr0, W0, b0, h1);
    sage_layer<1><<<B_TARGETS / BM, THREADS, SMEM>>>(
        h1, nullptr, nullptr, nullptr, W1, b1, out);
}

// round 5
// speedup vs baseline: 1.1678x; 1.1678x over previous
#include <cuda_runtime.h>
#include <cstddef>

#define THREADS   256
#define SXS       258    // 256 + 2 pad: even -> 8B-aligned b64 LDS, odd/2 -> low conflict
#define SWS       66     // 64 + 2 pad
#define B_TARGETS 4096
#define L1_ROWS   (B_TARGETS * 11)   // 45056

// Layer-1 hidden representations scratch (23 MB).
__device__ __align__(256) float g_h1[L1_ROWS * 128];

typedef unsigned long long u64;

// Packed dual-fp32 FMA (Blackwell f32x2): d = a*b + d elementwise on pairs.
__device__ __forceinline__ void ffma2(u64& d, u64 a, u64 b) {
    asm("fma.rn.f32x2 %0, %1, %2, %0;" : "+l"(d) : "l"(a), "l"(b));
}
__device__ __forceinline__ float2 unpack2(u64 v) {
    float2 r;
    asm("mov.b64 {%0, %1}, %2;" : "=f"(r.x), "=f"(r.y) : "l"(v));
    return r;
}

// Fused: build X tile [BM x 256] in shared (gather + mean), then
// Y = l2norm_rows(relu(X @ W^T + bias)), Y is [BM x 128].
// LAYER 0: X rows are level-1 nodes (self feat || mean of 25 nbr feats).
// LAYER 1: X rows are targets       (h1[b,0]   || mean of h1[b,1..10]).
// MI = output rows per thread; BM = 16*MI; 256 threads = 16(nt) x 16(mt).
template <int LAYER, int MI>
__global__ __launch_bounds__(THREADS, 2)
void sage_layer(const float* __restrict__ src,
                const int*   __restrict__ nodes,
                const int*   __restrict__ nbr1,
                const int*   __restrict__ nbr0,
                const float* __restrict__ W,      // [128][256] row-major
                const float* __restrict__ bias,   // [128]
                float*       __restrict__ out)    // [rows][128]
{
    constexpr int BM = 16 * MI;
    extern __shared__ float smem[];
    float* sX    = smem;                   // BM * SXS
    float* sW    = sX + BM * SXS;          // 128 * SWS
    float* sBias = sW + 128 * SWS;         // 128
    float* sPart = sBias + 128;            // 16 * BM
    float* sInv  = sPart + 16 * BM;        // BM

    const int tid  = threadIdx.x;
    const int warp = tid >> 5;
    const int lane = tid & 31;
    const int m0   = blockIdx.x * BM;

    if (tid < 128) sBias[tid] = bias[tid];

    // ---------------- gather: warp w builds rows w*RPW .. w*RPW+RPW-1 -------
    constexpr int RPW = BM / 8;
    #pragma unroll
    for (int r = 0; r < RPW; ++r) {
        const int mL = warp * RPW + r;
        float4 self;
        float4 acc = make_float4(0.f, 0.f, 0.f, 0.f);

        if (LAYER == 0) {
            const int j   = m0 + mL;          // level-1 node id
            const int b   = j / 11;
            const int col = j - b * 11;
            const int sidx = (col == 0) ? __ldg(&nodes[b])
                                        : __ldg(&nbr1[b * 10 + col - 1]);
            self = ((const float4*)(src + (size_t)sidx * 128))[lane];

            const int* nb = nbr0 + (size_t)j * 25;
            int myidx = (lane < 25) ? __ldg(&nb[lane]) : 0;   // 1 LDG, then shfl
            #pragma unroll
            for (int s = 0; s < 25; ++s) {
                const int ni = __shfl_sync(0xffffffffu, myidx, s);
                float4 v = ((const float4*)(src + (size_t)ni * 128))[lane];
                acc.x += v.x; acc.y += v.y; acc.z += v.z; acc.w += v.w;
            }
            const float sc = 1.0f / 25.0f;
            acc.x *= sc; acc.y *= sc; acc.z *= sc; acc.w *= sc;
        } else {
            const int b = m0 + mL;            // target index
            const float* base = src + (size_t)b * (11 * 128);
            self = ((const float4*)base)[lane];
            #pragma unroll
            for (int s = 1; s <= 10; ++s) {
                float4 v = ((const float4*)(base + s * 128))[lane];
                acc.x += v.x; acc.y += v.y; acc.z += v.z; acc.w += v.w;
            }
            const float sc = 0.1f;
            acc.x *= sc; acc.y *= sc; acc.z *= sc; acc.w *= sc;
        }

        float* dst = sX + mL * SXS;           // row base always 8B-aligned (258 even)
        ((float2*)dst)[2 * lane + 0]      = make_float2(self.x, self.y);
        ((float2*)dst)[2 * lane + 1]      = make_float2(self.z, self.w);
        ((float2*)(dst + 128))[2 * lane + 0] = make_float2(acc.x, acc.y);
        ((float2*)(dst + 128))[2 * lane + 1] = make_float2(acc.z, acc.w);
    }

    // ---------------- GEMM with packed f32x2: acc2 pairs = (even-k, odd-k) --
    const int nt = tid >> 4;   // 0..15 : output col group (j = nt*8 .. +7)
    const int mt = tid & 15;   // 0..15 : row group (rows mt*MI .. +MI-1)

    u64 acc2[MI][8];
    #pragma unroll
    for (int mi = 0; mi < MI; ++mi)
        #pragma unroll
        for (int j = 0; j < 8; ++j) acc2[mi][j] = 0ull;

    #pragma unroll 1
    for (int kc = 0; kc < 4; ++kc) {
        __syncthreads();   // kc==0: gather done; kc>0: protect sW overwrite
        for (int i = tid; i < 128 * 64; i += THREADS) {
            const int h = i >> 6, kk = i & 63;
            sW[h * SWS + kk] = __ldg(&W[h * 256 + kc * 64 + kk]);
        }
        __syncthreads();

        const float* bp = sW + (nt * 8) * SWS;
        const float* ap = sX + (mt * MI) * SXS + kc * 64;

        #pragma unroll 4
        for (int kk2 = 0; kk2 < 32; ++kk2) {
            u64 bv[8];
            #pragma unroll
            for (int j = 0; j < 8; ++j)
                bv[j] = *(const u64*)(bp + j * SWS + 2 * kk2);
            #pragma unroll
            for (int mi = 0; mi < MI; ++mi) {
                const u64 av = *(const u64*)(ap + mi * SXS + 2 * kk2);
                #pragma unroll
                for (int j = 0; j < 8; ++j) ffma2(acc2[mi][j], av, bv[j]);
            }
        }
    }

    // ---------------- epilogue: bias + relu + row L2 norm + store ----------
    float vals[MI][8];
    #pragma unroll
    for (int mi = 0; mi < MI; ++mi) {
        float ss = 0.f;
        #pragma unroll
        for (int j = 0; j < 8; ++j) {
            const float2 p = unpack2(acc2[mi][j]);
            const float v = fmaxf(p.x + p.y + sBias[nt * 8 + j], 0.f);
            vals[mi][j] = v;
            ss += v * v;
        }
        sPart[nt * BM + mt * MI + mi] = ss;
    }
    __syncthreads();

    if (tid < BM) {
        float t = 0.f;
        #pragma unroll
        for (int n = 0; n < 16; ++n) t += sPart[n * BM + tid];
        sInv[tid] = 1.0f / fmaxf(sqrtf(t), 1e-12f);
    }
    __syncthreads();

    #pragma unroll
    for (int mi = 0; mi < MI; ++mi) {
        const int m = mt * MI + mi;
        const float inv = sInv[m];
        float* op = out + (size_t)(m0 + m) * 128 + nt * 8;
        ((float4*)op)[0] = make_float4(vals[mi][0] * inv, vals[mi][1] * inv,
                                       vals[mi][2] * inv, vals[mi][3] * inv);
        ((float4*)op)[1] = make_float4(vals[mi][4] * inv, vals[mi][5] * inv,
                                       vals[mi][6] * inv, vals[mi][7] * inv);
    }
}

extern "C" void kernel_launch(void* const* d_in, const int* in_sizes, int n_in,
                              void* d_out, int out_size)
{
    (void)in_sizes; (void)n_in; (void)out_size;

    const float* features = (const float*)d_in[0];
    const float* W0       = (const float*)d_in[1];
    const float* b0       = (const float*)d_in[2];
    const float* W1       = (const float*)d_in[3];
    const float* b1       = (const float*)d_in[4];
    const int*   nodes    = (const int*)d_in[5];
    const int*   nbr1     = (const int*)d_in[6];
    const int*   nbr0     = (const int*)d_in[7];
    float*       out      = (float*)d_out;

    const int SMEM0 = (64 * SXS + 128 * SWS + 128 + 16 * 64 + 64) * (int)sizeof(float);
    const int SMEM1 = (32 * SXS + 128 * SWS + 128 + 16 * 32 + 32) * (int)sizeof(float);

    cudaFuncSetAttribute(sage_layer<0, 4>,
                         cudaFuncAttributeMaxDynamicSharedMemorySize, SMEM0);
    cudaFuncSetAttribute(sage_layer<1, 2>,
                         cudaFuncAttributeMaxDynamicSharedMemorySize, SMEM1);

    float* h1 = nullptr;
    cudaGetSymbolAddress((void**)&h1, g_h1);

    sage_layer<0, 4><<<L1_ROWS / 64, THREADS, SMEM0>>>(
        features, nodes, nbr1, nbr0, W0, b0, h1);
    sage_layer<1, 2><<<B_TARGETS / 32, THREADS, SMEM1>>>(
        h1, nullptr, nullptr, nullptr, W1, b1, out);
}

// round 6
// speedup vs baseline: 1.4633x; 1.2530x over previous
#include <cuda_runtime.h>
#include <cstddef>
#include <cstdint>

#define THREADS   256
#define SXS       258    // X stride: 256 + 2 pad (even -> 8B-aligned LDS.64)
#define SWS       66     // W stride: 64 + 2 pad (B-side LDS conflict-free)
#define B_TARGETS 4096
#define L1_ROWS   (B_TARGETS * 11)   // 45056

// Layer-1 hidden representations scratch (23 MB).
__device__ __align__(256) float g_h1[L1_ROWS * 128];

typedef unsigned long long u64;

__device__ __forceinline__ void ffma2(u64& d, u64 a, u64 b) {
    asm("fma.rn.f32x2 %0, %1, %2, %0;" : "+l"(d) : "l"(a), "l"(b));
}
__device__ __forceinline__ float2 unpack2(u64 v) {
    float2 r;
    asm("mov.b64 {%0, %1}, %2;" : "=f"(r.x), "=f"(r.y) : "l"(v));
    return r;
}
__device__ __forceinline__ void cpa8(uint32_t dst, const float* src) {
    asm volatile("cp.async.ca.shared.global [%0], [%1], 8;"
                 :: "r"(dst), "l"(src));
}
__device__ __forceinline__ void cpa_commit() {
    asm volatile("cp.async.commit_group;");
}
__device__ __forceinline__ void cpa_wait_all() {
    asm volatile("cp.async.wait_group 0;");
}

// Fused: build X tile [BM x 256] in shared (gather + mean), then
// Y = l2norm_rows(relu(X @ W^T + bias)).  BM = 16*MI, 256 threads = 16nt x 16mt.
// LAYER 0: rows are level-1 nodes (self feat || mean of 25 nbr feats).
// LAYER 1: rows are targets       (h1[b,0]   || mean of h1[b,1..10]).
// W is staged in 4 K-chunks of 64, double-buffered via cp.async.
template <int LAYER, int MI>
__global__ __launch_bounds__(THREADS, 2)
void sage_layer(const float* __restrict__ src,
                const int*   __restrict__ nodes,
                const int*   __restrict__ nbr1,
                const int*   __restrict__ nbr0,
                const float* __restrict__ W,      // [128][256] row-major
                const float* __restrict__ bias,   // [128]
                float*       __restrict__ out)    // [rows][128]
{
    constexpr int BM = 16 * MI;
    extern __shared__ float smem[];
    float* sX    = smem;                    // BM * SXS
    float* sW    = sX + BM * SXS;           // 2 * 128 * SWS (double buffer)
    float* sBias = sW + 2 * 128 * SWS;      // 128
    float* sPart = sBias + 128;             // 16 * BM
    float* sInv  = sPart + 16 * BM;         // BM

    const int tid  = threadIdx.x;
    const int warp = tid >> 5;
    const int lane = tid & 31;
    const int m0   = blockIdx.x * BM;

    const uint32_t sWu =
        static_cast<uint32_t>(__cvta_generic_to_shared(sW));

    // Stage W chunk kc into buffer b (all 256 threads; 8B cp.async).
    auto load_chunk = [&](int kc, int b) {
        const float* wsrc = W + kc * 64;
        const uint32_t dst = sWu + (uint32_t)b * (128 * SWS * 4);
        #pragma unroll
        for (int t = 0; t < 16; ++t) {
            const int e  = tid + t * THREADS;   // 0..4095
            const int h  = e >> 5;              // 0..127
            const int c2 = e & 31;              // 8B pair index within 64 cols
            cpa8(dst + (uint32_t)(h * SWS + c2 * 2) * 4,
                 wsrc + h * 256 + c2 * 2);
        }
        cpa_commit();
    };

    load_chunk(0, 0);                        // hides under the gather below

    if (tid < 128) sBias[tid] = bias[tid];

    // ---------------- gather: warp w builds rows w*RPW .. w*RPW+RPW-1 -------
    constexpr int RPW = BM / 8;
    #pragma unroll
    for (int r = 0; r < RPW; ++r) {
        const int mL = warp * RPW + r;
        float4 self;
        float4 acc = make_float4(0.f, 0.f, 0.f, 0.f);

        if (LAYER == 0) {
            const int j   = m0 + mL;          // level-1 node id
            const int b   = j / 11;
            const int col = j - b * 11;
            const int sidx = (col == 0) ? __ldg(&nodes[b])
                                        : __ldg(&nbr1[b * 10 + col - 1]);
            self = ((const float4*)(src + (size_t)sidx * 128))[lane];

            const int* nb = nbr0 + (size_t)j * 25;
            int myidx = (lane < 25) ? __ldg(&nb[lane]) : 0;
            #pragma unroll
            for (int s = 0; s < 25; ++s) {
                const int ni = __shfl_sync(0xffffffffu, myidx, s);
                float4 v = ((const float4*)(src + (size_t)ni * 128))[lane];
                acc.x += v.x; acc.y += v.y; acc.z += v.z; acc.w += v.w;
            }
            const float sc = 1.0f / 25.0f;
            acc.x *= sc; acc.y *= sc; acc.z *= sc; acc.w *= sc;
        } else {
            const int b = m0 + mL;
            const float* base = src + (size_t)b * (11 * 128);
            self = ((const float4*)base)[lane];
            #pragma unroll
            for (int s = 1; s <= 10; ++s) {
                float4 v = ((const float4*)(base + s * 128))[lane];
                acc.x += v.x; acc.y += v.y; acc.z += v.z; acc.w += v.w;
            }
            const float sc = 0.1f;
            acc.x *= sc; acc.y *= sc; acc.z *= sc; acc.w *= sc;
        }

        float* dst = sX + mL * SXS;
        ((float2*)dst)[2 * lane + 0]         = make_float2(self.x, self.y);
        ((float2*)dst)[2 * lane + 1]         = make_float2(self.z, self.w);
        ((float2*)(dst + 128))[2 * lane + 0] = make_float2(acc.x, acc.y);
        ((float2*)(dst + 128))[2 * lane + 1] = make_float2(acc.z, acc.w);
    }

    // ---------------- GEMM, packed f32x2, pipelined W chunks ---------------
    const int nt = tid >> 4;   // 0..15 : cols nt*8 .. +7
    const int mt = tid & 15;   // 0..15 : rows mt*MI .. +MI-1

    u64 acc2[MI][8];
    #pragma unroll
    for (int mi = 0; mi < MI; ++mi)
        #pragma unroll
        for (int j = 0; j < 8; ++j) acc2[mi][j] = 0ull;

    #pragma unroll 1
    for (int kc = 0; kc < 4; ++kc) {
        cpa_wait_all();        // chunk kc landed (this thread's part)
        __syncthreads();       // publish cp.async data + (kc==0) gather; also
                               // guarantees everyone finished reading the
                               // buffer about to be overwritten below
        if (kc < 3) load_chunk(kc + 1, (kc + 1) & 1);   // overlaps compute

        const float* bp = sW + (size_t)(kc & 1) * (128 * SWS) + (nt * 8) * SWS;
        const float* ap = sX + (mt * MI) * SXS + kc * 64;

        #pragma unroll 4
        for (int kk2 = 0; kk2 < 32; ++kk2) {
            u64 bv[8];
            #pragma unroll
            for (int j = 0; j < 8; ++j)
                bv[j] = *(const u64*)(bp + j * SWS + 2 * kk2);
            #pragma unroll
            for (int mi = 0; mi < MI; ++mi) {
                const u64 av = *(const u64*)(ap + mi * SXS + 2 * kk2);
                #pragma unroll
                for (int j = 0; j < 8; ++j) ffma2(acc2[mi][j], av, bv[j]);
            }
        }
    }

    // ---------------- epilogue: bias + relu + row L2 norm + store ----------
    float vals[MI][8];
    #pragma unroll
    for (int mi = 0; mi < MI; ++mi) {
        float ss = 0.f;
        #pragma unroll
        for (int j = 0; j < 8; ++j) {
            const float2 p = unpack2(acc2[mi][j]);
            const float v = fmaxf(p.x + p.y + sBias[nt * 8 + j], 0.f);
            vals[mi][j] = v;
            ss += v * v;
        }
        sPart[nt * BM + mt * MI + mi] = ss;
    }
    __syncthreads();

    if (tid < BM) {
        float t = 0.f;
        #pragma unroll
        for (int n = 0; n < 16; ++n) t += sPart[n * BM + tid];
        sInv[tid] = 1.0f / fmaxf(sqrtf(t), 1e-12f);
    }
    __syncthreads();

    #pragma unroll
    for (int mi = 0; mi < MI; ++mi) {
        const int m = mt * MI + mi;
        const float inv = sInv[m];
        float* op = out + (size_t)(m0 + m) * 128 + nt * 8;
        ((float4*)op)[0] = make_float4(vals[mi][0] * inv, vals[mi][1] * inv,
                                       vals[mi][2] * inv, vals[mi][3] * inv);
        ((float4*)op)[1] = make_float4(vals[mi][4] * inv, vals[mi][5] * inv,
                                       vals[mi][6] * inv, vals[mi][7] * inv);
    }
}

extern "C" void kernel_launch(void* const* d_in, const int* in_sizes, int n_in,
                              void* d_out, int out_size)
{
    (void)in_sizes; (void)n_in; (void)out_size;

    const float* features = (const float*)d_in[0];
    const float* W0       = (const float*)d_in[1];
    const float* b0       = (const float*)d_in[2];
    const float* W1       = (const float*)d_in[3];
    const float* b1       = (const float*)d_in[4];
    const int*   nodes    = (const int*)d_in[5];
    const int*   nbr1     = (const int*)d_in[6];
    const int*   nbr0     = (const int*)d_in[7];
    float*       out      = (float*)d_out;

    // floats: BM*SXS + 2*128*SWS + 128 + 16*BM + BM
    const int SMEM0 = (32 * SXS + 2 * 128 * SWS + 128 + 16 * 32 + 32)
                      * (int)sizeof(float);   // 103,296 B  (occ 2)
    const int SMEM1 = (16 * SXS + 2 * 128 * SWS + 128 + 16 * 16 + 16)
                      * (int)sizeof(float);   //  85,696 B  (occ 2)

    cudaFuncSetAttribute(sage_layer<0, 2>,
                         cudaFuncAttributeMaxDynamicSharedMemorySize, SMEM0);
    cudaFuncSetAttribute(sage_layer<0, 2>,
                         cudaFuncAttributePreferredSharedMemoryCarveout, 100);
    cudaFuncSetAttribute(sage_layer<1, 1>,
                         cudaFuncAttributeMaxDynamicSharedMemorySize, SMEM1);
    cudaFuncSetAttribute(sage_layer<1, 1>,
                         cudaFuncAttributePreferredSharedMemoryCarveout, 100);

    float* h1 = nullptr;
    cudaGetSymbolAddress((void**)&h1, g_h1);

    sage_layer<0, 2><<<L1_ROWS / 32, THREADS, SMEM0>>>(
        features, nodes, nbr1, nbr0, W0, b0, h1);
    sage_layer<1, 1><<<B_TARGETS / 16, THREADS, SMEM1>>>(
        h1, nullptr, nullptr, nullptr, W1, b1, out);
}